// round 1
// baseline (speedup 1.0000x reference)
#include <cuda_runtime.h>
#include <math.h>

// ---------------------------------------------------------------------------
// SLAMv2: 14-layer MoE-attention transformer, fp32, segmented schedule.
// B=2, S=1024, D=1000, E=20 experts, HD=50 (E*HD==D), F=2048, CYCLES=3.
// ---------------------------------------------------------------------------

namespace {
constexpr int B = 2, S = 1024, D = 1000, E = 20, HD = 50, TH = 3 * HD;
constexpr int F = 2048, CYCLES = 3;

constexpr long long NX = (long long)B * S * D;                 // 2,048,000
constexpr long long OFF_X    = 0;
constexpr long long OFF_XNEW = OFF_X + NX;
constexpr long long OFF_T    = OFF_XNEW + NX;
constexpr long long OFF_X1   = OFF_T + NX;
constexpr long long OFF_Y    = OFF_X1 + NX;
constexpr long long OFF_A    = OFF_Y + NX;
constexpr long long OFF_ROUT = OFF_A + NX;                     // B*S*E
constexpr long long OFF_H    = OFF_ROUT + (long long)B * S * E;     // B*S*F
constexpr long long OFF_QKV  = OFF_H + (long long)B * S * F;        // B*E*S*TH
constexpr long long OFF_SC   = OFF_QKV + (long long)B * E * S * TH; // B*E*S*S
constexpr long long TOTAL    = OFF_SC + (long long)B * E * S * S;

// Segment schedule for S=1024 (matches reference int() math exactly):
// bounds: (0,460) (256,665) (460,870) (665,1024)+wrap 51
constexpr int SEG_ST[4] = {0, 256, 460, 665};
constexpr int SEG_N[4]  = {460, 409, 410, 410};
constexpr int SEG_P1[4] = {460, 409, 410, 359};  // part-1 length (wrap split for seg 3)
}  // namespace

__device__ float g_scratch[TOTAL];

// ---------------------------------------------------------------------------
// Generic batched SGEMM. C = A*B (+bias) with z-batching via div/mod strides.
//   off(ptr, z) = (z / div)*s1 + (z % div)*s2
// BTRANS: 0 -> B is [K,N] row-major; 1 -> B is [N,K] row-major (C = A*B^T)
// EPI: 0 = +bias; 1 = +bias then exact GELU; 2 = *scale; 3 = *routing weight
// ---------------------------------------------------------------------------
struct GemmP {
  const float* A; const float* Bm; const float* bias; float* C;
  int M, N, K, lda, ldb, ldc;
  int aDiv; long long as1, as2;
  int bDiv; long long bs1, bs2;
  int cDiv; long long cs1, cs2;
  int biasDiv; long long biasS;
  float scale;
  const float* rout; int routN;
};

template <int BM, int BN, int BK, int TM, int TN, int BTRANS, int EPI>
__global__ __launch_bounds__((BM / TM) * (BN / TN)) void sgemm_k(GemmP p) {
  constexpr int NTHR = (BM / TM) * (BN / TN);
  constexpr int TX = BN / TN;
  __shared__ float As[BK][BM];
  __shared__ float Bs[BK][BN];

  const int z = blockIdx.z;
  const float* Ab = p.A + (long long)(z / p.aDiv) * p.as1 + (long long)(z % p.aDiv) * p.as2;
  const float* Bb = p.Bm + (long long)(z / p.bDiv) * p.bs1 + (long long)(z % p.bDiv) * p.bs2;
  float* Cb = p.C + (long long)(z / p.cDiv) * p.cs1 + (long long)(z % p.cDiv) * p.cs2;

  const int m0 = blockIdx.y * BM, n0 = blockIdx.x * BN;
  const int tid = threadIdx.x;
  const int tx = tid % TX, ty = tid / TX;

  float acc[TM][TN];
#pragma unroll
  for (int i = 0; i < TM; i++)
#pragma unroll
    for (int j = 0; j < TN; j++) acc[i][j] = 0.f;

  for (int k0 = 0; k0 < p.K; k0 += BK) {
    // Load A tile -> As[k][m] (transposed for conflict-free compute reads)
    for (int idx = tid; idx < BM * BK; idx += NTHR) {
      int m = idx / BK, kk = idx % BK;
      int gm = m0 + m, gk = k0 + kk;
      As[kk][m] = (gm < p.M && gk < p.K) ? Ab[(long long)gm * p.lda + gk] : 0.f;
    }
    // Load B tile -> Bs[k][n]
    if (BTRANS == 0) {
      for (int idx = tid; idx < BK * BN; idx += NTHR) {
        int kk = idx / BN, nn = idx % BN;
        int gk = k0 + kk, gn = n0 + nn;
        Bs[kk][nn] = (gk < p.K && gn < p.N) ? Bb[(long long)gk * p.ldb + gn] : 0.f;
      }
    } else {
      for (int idx = tid; idx < BK * BN; idx += NTHR) {
        int nn = idx / BK, kk = idx % BK;
        int gk = k0 + kk, gn = n0 + nn;
        Bs[kk][nn] = (gk < p.K && gn < p.N) ? Bb[(long long)gn * p.ldb + gk] : 0.f;
      }
    }
    __syncthreads();

#pragma unroll
    for (int kk = 0; kk < BK; kk++) {
      float a[TM], b[TN];
#pragma unroll
      for (int i = 0; i < TM; i += 4)
        *reinterpret_cast<float4*>(&a[i]) =
            *reinterpret_cast<const float4*>(&As[kk][ty * TM + i]);
#pragma unroll
      for (int j = 0; j < TN; j += 4)
        *reinterpret_cast<float4*>(&b[j]) =
            *reinterpret_cast<const float4*>(&Bs[kk][tx * TN + j]);
#pragma unroll
      for (int i = 0; i < TM; i++)
#pragma unroll
        for (int j = 0; j < TN; j++) acc[i][j] += a[i] * b[j];
    }
    __syncthreads();
  }

  const float* biasb =
      (EPI <= 1 && p.bias) ? p.bias + (long long)(z % p.biasDiv) * p.biasS : nullptr;

#pragma unroll
  for (int i = 0; i < TM; i++) {
    int row = m0 + ty * TM + i;
    if (row < p.M) {
#pragma unroll
      for (int j = 0; j < TN; j++) {
        int col = n0 + tx * TN + j;
        if (col < p.N) {
          float v = acc[i][j];
          if (EPI == 0 || EPI == 1) {
            if (biasb) v += biasb[col];
          }
          if (EPI == 1) v = 0.5f * v * (1.f + erff(v * 0.70710678118654752f));
          if (EPI == 2) v *= p.scale;
          if (EPI == 3)
            v *= p.rout[((long long)(z / p.cDiv) * p.routN + row) * E + (z % p.cDiv)];
          Cb[(long long)row * p.ldc + col] = v;
        }
      }
    }
  }
}

// ---------------------------------------------------------------------------
// Small kernels
// ---------------------------------------------------------------------------
__global__ void copy_k(float* dst, const float* src, long long n) {
  long long i = (long long)blockIdx.x * blockDim.x + threadIdx.x;
  if (i < n) dst[i] = src[i];
}

__global__ void zero_k(float* dst, long long n) {
  long long i = (long long)blockIdx.x * blockDim.x + threadIdx.x;
  if (i < n) dst[i] = 0.f;
}

__global__ void gather_k(float* dst, const float* src, int nseg, int st, int p1) {
  long long i = (long long)blockIdx.x * blockDim.x + threadIdx.x;
  long long tot = (long long)B * nseg * D;
  if (i >= tot) return;
  int d = (int)(i % D);
  long long r = i / D;
  int ii = (int)(r % nseg);
  int b_ = (int)(r / nseg);
  int si = (ii < p1) ? (st + ii) : (ii - p1);
  dst[i] = src[((long long)b_ * S + si) * D + d];
}

__global__ void scatter_add_k(float* dst, const float* src, int nseg, int st, int p1) {
  long long i = (long long)blockIdx.x * blockDim.x + threadIdx.x;
  long long tot = (long long)B * nseg * D;
  if (i >= tot) return;
  int d = (int)(i % D);
  long long r = i / D;
  int ii = (int)(r % nseg);
  int b_ = (int)(r / nseg);
  int si = (ii < p1) ? (st + ii) : (ii - p1);
  dst[((long long)b_ * S + si) * D + d] += src[i];
}

__device__ __forceinline__ float seg_cnt(int i) {
  float c = 0.f;
  c += (i < 460);
  c += (i >= 256 && i < 665);
  c += (i >= 460 && i < 870);
  c += (i >= 665);
  c += (i < 51);
  return c;
}

__global__ void div_counts_k(float* x, const float* xn) {
  long long i = (long long)blockIdx.x * blockDim.x + threadIdx.x;
  if (i >= NX) return;
  int ii = (int)((i / D) % S);
  x[i] = xn[i] / seg_cnt(ii);
}

// Routing softmax over E=20 experts; one thread per (b, s) row.
__global__ void softmaxE_k(float* r, int rows) {
  int i = blockIdx.x * blockDim.x + threadIdx.x;
  if (i >= rows) return;
  float* p = r + (long long)i * E;
  float m = -1e30f;
  for (int e = 0; e < E; e++) m = fmaxf(m, p[e]);
  float s = 0.f;
  for (int e = 0; e < E; e++) {
    float v = expf(p[e] - m);
    p[e] = v;
    s += v;
  }
  float inv = 1.f / s;
  for (int e = 0; e < E; e++) p[e] *= inv;
}

// In-place row softmax over attention scores. grid = (n rows, B*E batches).
__global__ void softmax_rows_k(float* s, int n) {
  float* row = s + ((long long)blockIdx.y * n + blockIdx.x) * n;
  __shared__ float red[32];
  __shared__ float bcast;
  int tid = threadIdx.x;
  int nw = blockDim.x >> 5;

  float m = -1e30f;
  for (int j = tid; j < n; j += blockDim.x) m = fmaxf(m, row[j]);
  for (int o = 16; o; o >>= 1) m = fmaxf(m, __shfl_xor_sync(0xffffffffu, m, o));
  if ((tid & 31) == 0) red[tid >> 5] = m;
  __syncthreads();
  if (tid < 32) {
    float v = (tid < nw) ? red[tid] : -1e30f;
    for (int o = 16; o; o >>= 1) v = fmaxf(v, __shfl_xor_sync(0xffffffffu, v, o));
    if (tid == 0) bcast = v;
  }
  __syncthreads();
  m = bcast;

  float sum = 0.f;
  for (int j = tid; j < n; j += blockDim.x) {
    float e = expf(row[j] - m);
    row[j] = e;
    sum += e;
  }
  for (int o = 16; o; o >>= 1) sum += __shfl_xor_sync(0xffffffffu, sum, o);
  if ((tid & 31) == 0) red[tid >> 5] = sum;
  __syncthreads();
  if (tid < 32) {
    float v = (tid < nw) ? red[tid] : 0.f;
    for (int o = 16; o; o >>= 1) v += __shfl_xor_sync(0xffffffffu, v, o);
    if (tid == 0) bcast = v;
  }
  __syncthreads();
  float inv = 1.f / bcast;
  for (int j = tid; j < n; j += blockDim.x) row[j] *= inv;
}

// out = layernorm(x + r) * g + b; one block per row of D=1000.
__global__ void add_ln_k(const float* x, const float* r, const float* g,
                         const float* b, float* out) {
  long long base = (long long)blockIdx.x * D;
  __shared__ float buf[D];
  __shared__ float redA[32], redB[32];
  __shared__ float sh_m, sh_inv;
  int tid = threadIdx.x;
  int nw = blockDim.x >> 5;

  float s = 0.f, s2 = 0.f;
  for (int d = tid; d < D; d += blockDim.x) {
    float v = x[base + d] + r[base + d];
    buf[d] = v;
    s += v;
    s2 += v * v;
  }
  for (int o = 16; o; o >>= 1) {
    s += __shfl_xor_sync(0xffffffffu, s, o);
    s2 += __shfl_xor_sync(0xffffffffu, s2, o);
  }
  if ((tid & 31) == 0) { redA[tid >> 5] = s; redB[tid >> 5] = s2; }
  __syncthreads();
  if (tid < 32) {
    float a2 = (tid < nw) ? redA[tid] : 0.f;
    float b2 = (tid < nw) ? redB[tid] : 0.f;
    for (int o = 16; o; o >>= 1) {
      a2 += __shfl_xor_sync(0xffffffffu, a2, o);
      b2 += __shfl_xor_sync(0xffffffffu, b2, o);
    }
    if (tid == 0) {
      float mean = a2 / D;
      float var = b2 / D - mean * mean;
      sh_m = mean;
      sh_inv = rsqrtf(var + 1e-5f);
    }
  }
  __syncthreads();
  float mean = sh_m, inv = sh_inv;
  for (int d = tid; d < D; d += blockDim.x)
    out[base + d] = (buf[d] - mean) * inv * g[d] + b[d];
}

// ---------------------------------------------------------------------------
// Host-side block driver (all launches are graph-capturable, default stream)
// ---------------------------------------------------------------------------
static inline int cdiv(int a, int b) { return (a + b - 1) / b; }

struct Wts {
  const float *ew, *eb, *rw, *rb, *ow, *ob, *l1g, *l1b, *w1, *b1, *w2, *b2, *l2g, *l2b;
};

static void run_block(float* sc, const float* t, float* out, int layer, int n,
                      const Wts& w) {
  const int M = B * n;
  float* rout = sc + OFF_ROUT;
  float* qkv = sc + OFF_QKV;
  float* sco = sc + OFF_SC;
  float* y = sc + OFF_Y;
  float* a = sc + OFF_A;
  float* x1 = sc + OFF_X1;
  float* h = sc + OFF_H;

  GemmP p;
  auto reset = [&]() {
    p = GemmP{};
    p.aDiv = p.bDiv = p.cDiv = p.biasDiv = 1;
    p.scale = 1.f;
  };

  // 1. routing logits + softmax over experts
  reset();
  p.A = t; p.Bm = w.rw + (long long)layer * D * E;
  p.bias = w.rb + (long long)layer * E; p.C = rout;
  p.M = M; p.N = E; p.K = D; p.lda = D; p.ldb = E; p.ldc = E;
  sgemm_k<128, 64, 8, 8, 4, 0, 0><<<dim3(1, cdiv(M, 128), 1), 256>>>(p);
  softmaxE_k<<<cdiv(M, 256), 256>>>(rout, M);

  // 2. qkv = t @ expert_w[e] + expert_b[e], batched over z = b*E + e
  reset();
  p.A = t; p.lda = D; p.aDiv = E; p.as1 = (long long)n * D;
  p.Bm = w.ew + (long long)layer * E * D * TH; p.ldb = TH;
  p.bDiv = E; p.bs2 = (long long)D * TH;
  p.bias = w.eb + (long long)layer * E * TH; p.biasDiv = E; p.biasS = TH;
  p.C = qkv; p.ldc = TH; p.cs1 = (long long)n * TH;
  p.M = n; p.N = TH; p.K = D;
  sgemm_k<128, 64, 8, 8, 4, 0, 0>
      <<<dim3(cdiv(TH, 64), cdiv(n, 128), B * E), 256>>>(p);

  // 3. scores = q @ k^T * HD^-0.5 (NT), batched over (b,e)
  reset();
  p.A = qkv; p.lda = TH; p.as1 = (long long)n * TH;
  p.Bm = qkv + HD; p.ldb = TH; p.bs1 = (long long)n * TH;
  p.C = sco; p.ldc = n; p.cs1 = (long long)n * n;
  p.M = n; p.N = n; p.K = HD;
  p.scale = 0.14142135623730950488f;  // 1/sqrt(50)
  sgemm_k<128, 128, 8, 8, 8, 1, 2>
      <<<dim3(cdiv(n, 128), cdiv(n, 128), B * E), 256>>>(p);

  softmax_rows_k<<<dim3(n, B * E), 256>>>(sco, n);

  // 4. y[:, e*HD:(e+1)*HD] = (P @ v) * routing[b, s, e]
  reset();
  p.A = sco; p.lda = n; p.as1 = (long long)n * n;
  p.Bm = qkv + 2 * HD; p.ldb = TH; p.bs1 = (long long)n * TH;
  p.C = y; p.ldc = D; p.cDiv = E; p.cs1 = (long long)n * D; p.cs2 = HD;
  p.M = n; p.N = HD; p.K = n;
  p.rout = rout; p.routN = n;
  sgemm_k<128, 64, 8, 8, 4, 0, 3><<<dim3(1, cdiv(n, 128), B * E), 256>>>(p);

  // 5. a = y @ out_w + out_b
  reset();
  p.A = y; p.lda = D;
  p.Bm = w.ow + (long long)layer * D * D; p.ldb = D;
  p.bias = w.ob + (long long)layer * D;
  p.C = a; p.ldc = D;
  p.M = M; p.N = D; p.K = D;
  sgemm_k<128, 128, 8, 8, 8, 0, 0>
      <<<dim3(cdiv(D, 128), cdiv(M, 128), 1), 256>>>(p);

  // 6. x1 = LN1(t + a)
  add_ln_k<<<M, 256>>>(t, a, w.l1g + (long long)layer * D,
                       w.l1b + (long long)layer * D, x1);

  // 7. h = gelu(x1 @ ff_w1 + ff_b1)
  reset();
  p.A = x1; p.lda = D;
  p.Bm = w.w1 + (long long)layer * D * F; p.ldb = F;
  p.bias = w.b1 + (long long)layer * F;
  p.C = h; p.ldc = F;
  p.M = M; p.N = F; p.K = D;
  sgemm_k<128, 128, 8, 8, 8, 0, 1>
      <<<dim3(cdiv(F, 128), cdiv(M, 128), 1), 256>>>(p);

  // 8. f = h @ ff_w2 + ff_b2 (into y, reuse)
  reset();
  p.A = h; p.lda = F;
  p.Bm = w.w2 + (long long)layer * F * D; p.ldb = D;
  p.bias = w.b2 + (long long)layer * D;
  p.C = y; p.ldc = D;
  p.M = M; p.N = D; p.K = F;
  sgemm_k<128, 128, 8, 8, 8, 0, 0>
      <<<dim3(cdiv(D, 128), cdiv(M, 128), 1), 256>>>(p);

  // 9. out = LN2(x1 + f)
  add_ln_k<<<M, 256>>>(x1, y, w.l2g + (long long)layer * D,
                       w.l2b + (long long)layer * D, out);
}

extern "C" void kernel_launch(void* const* d_in, const int* in_sizes, int n_in,
                              void* d_out, int out_size) {
  (void)in_sizes; (void)n_in; (void)out_size;
  float* sc = nullptr;
  cudaGetSymbolAddress((void**)&sc, g_scratch);

  const float* x_in = (const float*)d_in[0];
  Wts w;
  w.ew = (const float*)d_in[1];  w.eb = (const float*)d_in[2];
  w.rw = (const float*)d_in[3];  w.rb = (const float*)d_in[4];
  w.ow = (const float*)d_in[5];  w.ob = (const float*)d_in[6];
  w.l1g = (const float*)d_in[7]; w.l1b = (const float*)d_in[8];
  w.w1 = (const float*)d_in[9];  w.b1 = (const float*)d_in[10];
  w.w2 = (const float*)d_in[11]; w.b2 = (const float*)d_in[12];
  w.l2g = (const float*)d_in[13]; w.l2b = (const float*)d_in[14];

  // x = input
  copy_k<<<cdiv((int)NX, 256), 256>>>(sc + OFF_X, x_in, NX);

  // Block 0 on full sequence (in-place output into X is safe: t unused by LN2)
  run_block(sc, sc + OFF_X, sc + OFF_X, 0, S, w);

  // 3 cycles x 4 overlapping segments
  for (int c = 0; c < CYCLES; c++) {
    zero_k<<<cdiv((int)NX, 256), 256>>>(sc + OFF_XNEW, NX);
    for (int j = 0; j < 4; j++) {
      int nseg = SEG_N[j];
      int tot = B * nseg * D;
      gather_k<<<cdiv(tot, 256), 256>>>(sc + OFF_T, sc + OFF_X, nseg, SEG_ST[j],
                                        SEG_P1[j]);
      run_block(sc, sc + OFF_T, sc + OFF_A, 1 + 4 * c + j, nseg, w);
      scatter_add_k<<<cdiv(tot, 256), 256>>>(sc + OFF_XNEW, sc + OFF_A, nseg,
                                             SEG_ST[j], SEG_P1[j]);
    }
    div_counts_k<<<cdiv((int)NX, 256), 256>>>(sc + OFF_X, sc + OFF_XNEW);
  }

  // Final block (layer 13) writes directly into d_out
  run_block(sc, sc + OFF_X, (float*)d_out, 13, S, w);
}

// round 2
// speedup vs baseline: 2.7558x; 2.7558x over previous
#include <cuda_runtime.h>
#include <math.h>

// ---------------------------------------------------------------------------
// SLAMv2: 14-layer MoE-attention transformer, fp32, segmented schedule.
// B=2, S=1024, D=1000, E=20 experts, HD=50 (E*HD==D), F=2048, CYCLES=3.
// Round 2: double-buffered vectorized SGEMM, padded QKV/score layouts.
// ---------------------------------------------------------------------------

namespace {
constexpr int B = 2, S = 1024, D = 1000, E = 20, HD = 50, TH = 3 * HD;
constexpr int HD_P = 52;  // padded head dim (16B-aligned rows)
constexpr int F = 2048, CYCLES = 3;

constexpr long long NX = (long long)B * S * D;  // 2,048,000
constexpr long long OFF_X    = 0;
constexpr long long OFF_XNEW = OFF_X + NX;
constexpr long long OFF_T    = OFF_XNEW + NX;
constexpr long long OFF_X1   = OFF_T + NX;
constexpr long long OFF_Y    = OFF_X1 + NX;
constexpr long long OFF_A    = OFF_Y + NX;
constexpr long long OFF_ROUT = OFF_A + NX;                       // B*S*E
constexpr long long OFF_H    = OFF_ROUT + (long long)B * S * E;  // B*S*F
constexpr long long OFF_QKV  = OFF_H + (long long)B * S * F;     // B*E*3*S*HD_P
constexpr long long OFF_SC   = OFF_QKV + (long long)B * E * 3 * S * HD_P;
constexpr long long TOTAL    = OFF_SC + (long long)B * E * S * S;

// Segment schedule for S=1024 (matches reference int() math):
// (0,460) (256,665) (460,870) (665,1024)+wrap 51
constexpr int SEG_ST[4] = {0, 256, 460, 665};
constexpr int SEG_N[4]  = {460, 409, 410, 410};
constexpr int SEG_P1[4] = {460, 409, 410, 359};
}  // namespace

__device__ float g_scratch[TOTAL];

// ---------------------------------------------------------------------------
// Double-buffered SGEMM. C = A*B (+epilogue), z-batched via div/mod strides.
// BTRANS: 0 -> B is [K,N]; 1 -> B is [N,K] (C = A*B^T).
// EPI: 0 +bias; 1 +bias,GELU; 2 *scale; 3 *routing; 4 +bias,split-QKV store.
// BALIGN: 0 -> B global loads always scalar (unaligned source rows).
// ---------------------------------------------------------------------------
struct GemmP {
  const float* A; const float* Bm; const float* bias; float* C;
  int M, N, K, lda, ldb, ldc;
  int aDiv; long long as1, as2;
  int bDiv; long long bs1, bs2;
  int cDiv; long long cs1, cs2;
  int biasDiv; long long biasS;
  long long splitStride;
  float scale;
  const float* rout; int routN;
};

template <int BM, int BN, int BK, int TM, int TN, int BTRANS, int EPI,
          int BALIGN = 1>
__global__ __launch_bounds__((BM / TM) * (BN / TN)) void sgemm2_k(GemmP p) {
  constexpr int NTHR = (BM / TM) * (BN / TN);
  constexpr int TX = BN / TN;
  constexpr int KV = BK / 4;
  constexpr int AVEC = (BM * BK) / (4 * NTHR);
  constexpr int BVEC = (BK * BN) / (4 * NTHR);
  constexpr int LDAS = BM + 4;
  constexpr int LDBS = BN + 4;
  __shared__ __align__(16) float As[2][BK][LDAS];
  __shared__ __align__(16) float Bs[2][BK][LDBS];

  const int z = blockIdx.z;
  const float* Ab =
      p.A + (long long)(z / p.aDiv) * p.as1 + (long long)(z % p.aDiv) * p.as2;
  const float* Bb =
      p.Bm + (long long)(z / p.bDiv) * p.bs1 + (long long)(z % p.bDiv) * p.bs2;
  float* Cb =
      p.C + (long long)(z / p.cDiv) * p.cs1 + (long long)(z % p.cDiv) * p.cs2;

  const int m0 = blockIdx.y * BM, n0 = blockIdx.x * BN;
  const int tid = threadIdx.x;
  const int tx = tid % TX, ty = tid / TX;

  float4 ar[AVEC];
  float4 br[BVEC];

  auto ldA = [&](int k0) {
#pragma unroll
    for (int v = 0; v < AVEC; v++) {
      int idx = tid + v * NTHR;
      int m = idx / KV, kk = (idx % KV) * 4;
      int gm = m0 + m, gk = k0 + kk;
      float4 r = {0.f, 0.f, 0.f, 0.f};
      if (gm < p.M) {
        const float* s = Ab + (long long)gm * p.lda + gk;
        if (gk + 3 < p.K) {
          r = *reinterpret_cast<const float4*>(s);
        } else {
          if (gk < p.K) r.x = s[0];
          if (gk + 1 < p.K) r.y = s[1];
          if (gk + 2 < p.K) r.z = s[2];
        }
      }
      ar[v] = r;
    }
  };
  auto stA = [&](int buf) {
#pragma unroll
    for (int v = 0; v < AVEC; v++) {
      int idx = tid + v * NTHR;
      int m = idx / KV, kk = (idx % KV) * 4;
      As[buf][kk + 0][m] = ar[v].x;
      As[buf][kk + 1][m] = ar[v].y;
      As[buf][kk + 2][m] = ar[v].z;
      As[buf][kk + 3][m] = ar[v].w;
    }
  };
  auto ldB = [&](int k0) {
    if (BTRANS == 0) {
#pragma unroll
      for (int v = 0; v < BVEC; v++) {
        int idx = tid + v * NTHR;
        int kk = idx / (BN / 4), nn = (idx % (BN / 4)) * 4;
        int gk = k0 + kk, gn = n0 + nn;
        float4 r = {0.f, 0.f, 0.f, 0.f};
        if (gk < p.K) {
          const float* s = Bb + (long long)gk * p.ldb + gn;
          if (BALIGN && gn + 3 < p.N) {
            r = *reinterpret_cast<const float4*>(s);
          } else {
            if (gn < p.N) r.x = s[0];
            if (gn + 1 < p.N) r.y = s[1];
            if (gn + 2 < p.N) r.z = s[2];
            if (gn + 3 < p.N) r.w = s[3];
          }
        }
        br[v] = r;
      }
    } else {
#pragma unroll
      for (int v = 0; v < BVEC; v++) {
        int idx = tid + v * NTHR;
        int nn = idx / KV, kk = (idx % KV) * 4;
        int gn = n0 + nn, gk = k0 + kk;
        float4 r = {0.f, 0.f, 0.f, 0.f};
        if (gn < p.N) {
          const float* s = Bb + (long long)gn * p.ldb + gk;
          if (gk + 3 < p.K) {
            r = *reinterpret_cast<const float4*>(s);
          } else {
            if (gk < p.K) r.x = s[0];
            if (gk + 1 < p.K) r.y = s[1];
            if (gk + 2 < p.K) r.z = s[2];
          }
        }
        br[v] = r;
      }
    }
  };
  auto stB = [&](int buf) {
    if (BTRANS == 0) {
#pragma unroll
      for (int v = 0; v < BVEC; v++) {
        int idx = tid + v * NTHR;
        int kk = idx / (BN / 4), nn = (idx % (BN / 4)) * 4;
        *reinterpret_cast<float4*>(&Bs[buf][kk][nn]) = br[v];
      }
    } else {
#pragma unroll
      for (int v = 0; v < BVEC; v++) {
        int idx = tid + v * NTHR;
        int nn = idx / KV, kk = (idx % KV) * 4;
        Bs[buf][kk + 0][nn] = br[v].x;
        Bs[buf][kk + 1][nn] = br[v].y;
        Bs[buf][kk + 2][nn] = br[v].z;
        Bs[buf][kk + 3][nn] = br[v].w;
      }
    }
  };

  float acc[TM][TN];
#pragma unroll
  for (int i = 0; i < TM; i++)
#pragma unroll
    for (int j = 0; j < TN; j++) acc[i][j] = 0.f;

  auto comp = [&](int buf) {
#pragma unroll
    for (int kk = 0; kk < BK; kk++) {
      float a[TM], b[TN];
#pragma unroll
      for (int i = 0; i < TM; i += 4)
        *reinterpret_cast<float4*>(&a[i]) =
            *reinterpret_cast<const float4*>(&As[buf][kk][ty * TM + i]);
#pragma unroll
      for (int j = 0; j < TN; j += 4)
        *reinterpret_cast<float4*>(&b[j]) =
            *reinterpret_cast<const float4*>(&Bs[buf][kk][tx * TN + j]);
#pragma unroll
      for (int i = 0; i < TM; i++)
#pragma unroll
        for (int j = 0; j < TN; j++) acc[i][j] += a[i] * b[j];
    }
  };

  const int iters = (p.K + BK - 1) / BK;
  ldA(0);
  ldB(0);
  stA(0);
  stB(0);
  __syncthreads();
  int buf = 0;
  for (int it = 1; it < iters; it++) {
    ldA(it * BK);
    ldB(it * BK);
    comp(buf);
    stA(buf ^ 1);
    stB(buf ^ 1);
    __syncthreads();
    buf ^= 1;
  }
  comp(buf);

  const float* biasb = nullptr;
  if ((EPI == 0 || EPI == 1 || EPI == 4) && p.bias)
    biasb = p.bias + (long long)(z % p.biasDiv) * p.biasS;

#pragma unroll
  for (int i = 0; i < TM; i++) {
    int row = m0 + ty * TM + i;
    if (row >= p.M) continue;
#pragma unroll
    for (int j = 0; j < TN; j++) {
      int col = n0 + tx * TN + j;
      if (col >= p.N) continue;
      float v = acc[i][j];
      if (biasb) v += biasb[col];
      if (EPI == 1) v = 0.5f * v * (1.f + erff(v * 0.70710678118654752f));
      if (EPI == 2) v *= p.scale;
      if (EPI == 3)
        v *= p.rout[((long long)(z / p.cDiv) * p.routN + row) * E + (z % p.cDiv)];
      if (EPI == 4) {
        int h = col / HD, s2 = col - h * HD;
        Cb[(long long)h * p.splitStride + (long long)row * p.ldc + s2] = v;
      } else {
        Cb[(long long)row * p.ldc + col] = v;
      }
    }
  }
}

// ---------------------------------------------------------------------------
// Small kernels
// ---------------------------------------------------------------------------
__global__ void copy_k(float* dst, const float* src, long long n) {
  long long i = (long long)blockIdx.x * blockDim.x + threadIdx.x;
  if (i < n) dst[i] = src[i];
}

__global__ void zero_k(float* dst, long long n) {
  long long i = (long long)blockIdx.x * blockDim.x + threadIdx.x;
  if (i < n) dst[i] = 0.f;
}

__global__ void gather_k(float* dst, const float* src, int nseg, int st, int p1) {
  long long i = (long long)blockIdx.x * blockDim.x + threadIdx.x;
  long long tot = (long long)B * nseg * D;
  if (i >= tot) return;
  int d = (int)(i % D);
  long long r = i / D;
  int ii = (int)(r % nseg);
  int b_ = (int)(r / nseg);
  int si = (ii < p1) ? (st + ii) : (ii - p1);
  dst[i] = src[((long long)b_ * S + si) * D + d];
}

__global__ void scatter_add_k(float* dst, const float* src, int nseg, int st, int p1) {
  long long i = (long long)blockIdx.x * blockDim.x + threadIdx.x;
  long long tot = (long long)B * nseg * D;
  if (i >= tot) return;
  int d = (int)(i % D);
  long long r = i / D;
  int ii = (int)(r % nseg);
  int b_ = (int)(r / nseg);
  int si = (ii < p1) ? (st + ii) : (ii - p1);
  dst[((long long)b_ * S + si) * D + d] += src[i];
}

__device__ __forceinline__ float seg_cnt(int i) {
  float c = 0.f;
  c += (i < 460);
  c += (i >= 256 && i < 665);
  c += (i >= 460 && i < 870);
  c += (i >= 665);
  c += (i < 51);
  return c;
}

__global__ void div_counts_k(float* x, const float* xn) {
  long long i = (long long)blockIdx.x * blockDim.x + threadIdx.x;
  if (i >= NX) return;
  int ii = (int)((i / D) % S);
  x[i] = xn[i] / seg_cnt(ii);
}

__global__ void softmaxE_k(float* r, int rows) {
  int i = blockIdx.x * blockDim.x + threadIdx.x;
  if (i >= rows) return;
  float* p = r + (long long)i * E;
  float m = -1e30f;
  for (int e = 0; e < E; e++) m = fmaxf(m, p[e]);
  float s = 0.f;
  for (int e = 0; e < E; e++) {
    float v = __expf(p[e] - m);
    p[e] = v;
    s += v;
  }
  float inv = 1.f / s;
  for (int e = 0; e < E; e++) p[e] *= inv;
}

// In-place row softmax. grid = (n rows, B*E); row length n, stride ld.
__global__ void softmax_rows_k(float* s, int n, int ld) {
  float* row = s + (long long)blockIdx.y * n * ld + (long long)blockIdx.x * ld;
  __shared__ float red[32];
  __shared__ float bcast;
  int tid = threadIdx.x;
  int nw = blockDim.x >> 5;

  float m = -1e30f;
  for (int j = tid; j < n; j += blockDim.x) m = fmaxf(m, row[j]);
  for (int o = 16; o; o >>= 1) m = fmaxf(m, __shfl_xor_sync(0xffffffffu, m, o));
  if ((tid & 31) == 0) red[tid >> 5] = m;
  __syncthreads();
  if (tid < 32) {
    float v = (tid < nw) ? red[tid] : -1e30f;
    for (int o = 16; o; o >>= 1) v = fmaxf(v, __shfl_xor_sync(0xffffffffu, v, o));
    if (tid == 0) bcast = v;
  }
  __syncthreads();
  m = bcast;

  float sum = 0.f;
  for (int j = tid; j < n; j += blockDim.x) {
    float e = __expf(row[j] - m);
    row[j] = e;
    sum += e;
  }
  for (int o = 16; o; o >>= 1) sum += __shfl_xor_sync(0xffffffffu, sum, o);
  if ((tid & 31) == 0) red[tid >> 5] = sum;
  __syncthreads();
  if (tid < 32) {
    float v = (tid < nw) ? red[tid] : 0.f;
    for (int o = 16; o; o >>= 1) v += __shfl_xor_sync(0xffffffffu, v, o);
    if (tid == 0) bcast = v;
  }
  __syncthreads();
  float inv = 1.f / bcast;
  for (int j = tid; j < n; j += blockDim.x) row[j] *= inv;
}

// out = layernorm(x + r) * g + b; one block per row of D.
__global__ void add_ln_k(const float* x, const float* r, const float* g,
                         const float* b, float* out) {
  long long base = (long long)blockIdx.x * D;
  __shared__ float buf[D];
  __shared__ float redA[32], redB[32];
  __shared__ float sh_m, sh_inv;
  int tid = threadIdx.x;
  int nw = blockDim.x >> 5;

  float s = 0.f, s2 = 0.f;
  for (int d = tid; d < D; d += blockDim.x) {
    float v = x[base + d] + r[base + d];
    buf[d] = v;
    s += v;
    s2 += v * v;
  }
  for (int o = 16; o; o >>= 1) {
    s += __shfl_xor_sync(0xffffffffu, s, o);
    s2 += __shfl_xor_sync(0xffffffffu, s2, o);
  }
  if ((tid & 31) == 0) { redA[tid >> 5] = s; redB[tid >> 5] = s2; }
  __syncthreads();
  if (tid < 32) {
    float a2 = (tid < nw) ? redA[tid] : 0.f;
    float b2 = (tid < nw) ? redB[tid] : 0.f;
    for (int o = 16; o; o >>= 1) {
      a2 += __shfl_xor_sync(0xffffffffu, a2, o);
      b2 += __shfl_xor_sync(0xffffffffu, b2, o);
    }
    if (tid == 0) {
      float mean = a2 / D;
      float var = b2 / D - mean * mean;
      sh_m = mean;
      sh_inv = rsqrtf(var + 1e-5f);
    }
  }
  __syncthreads();
  float mean = sh_m, inv = sh_inv;
  for (int d = tid; d < D; d += blockDim.x)
    out[base + d] = (buf[d] - mean) * inv * g[d] + b[d];
}

// ---------------------------------------------------------------------------
// Host-side driver
// ---------------------------------------------------------------------------
static inline int cdiv(int a, int b) { return (a + b - 1) / b; }

struct Wts {
  const float *ew, *eb, *rw, *rb, *ow, *ob, *l1g, *l1b, *w1, *b1, *w2, *b2,
      *l2g, *l2b;
};

static void run_block(float* sc, const float* t, float* out, int layer, int n,
                      const Wts& w) {
  const int M = B * n;
  const int n4 = (n + 3) & ~3;
  float* rout = sc + OFF_ROUT;
  float* qkv = sc + OFF_QKV;
  float* sco = sc + OFF_SC;
  float* y = sc + OFF_Y;
  float* a = sc + OFF_A;
  float* x1 = sc + OFF_X1;
  float* h = sc + OFF_H;

  GemmP p;
  auto reset = [&]() {
    p = GemmP{};
    p.aDiv = p.bDiv = p.cDiv = p.biasDiv = 1;
    p.scale = 1.f;
  };

  // 1. routing logits + softmax over experts
  reset();
  p.A = t; p.Bm = w.rw + (long long)layer * D * E;
  p.bias = w.rb + (long long)layer * E; p.C = rout;
  p.M = M; p.N = E; p.K = D; p.lda = D; p.ldb = E; p.ldc = E;
  sgemm2_k<64, 64, 16, 4, 4, 0, 0><<<dim3(1, cdiv(M, 64), 1), 256>>>(p);
  softmaxE_k<<<cdiv(M, 256), 256>>>(rout, M);

  // 2. qkv = t @ expert_w[e] + expert_b[e], split-stored as Q/K/V [z][3][n][52]
  reset();
  p.A = t; p.lda = D; p.aDiv = E; p.as1 = (long long)n * D;
  p.Bm = w.ew + (long long)layer * E * D * TH; p.ldb = TH;
  p.bDiv = E; p.bs2 = (long long)D * TH;
  p.bias = w.eb + (long long)layer * E * TH; p.biasDiv = E; p.biasS = TH;
  p.C = qkv; p.ldc = HD_P; p.cs1 = 3LL * n * HD_P;
  p.splitStride = (long long)n * HD_P;
  p.M = n; p.N = TH; p.K = D;
  sgemm2_k<128, 64, 16, 8, 4, 0, 4, 0>
      <<<dim3(cdiv(TH, 64), cdiv(n, 128), B * E), 256>>>(p);

  // 3. scores = Q @ K^T * HD^-0.5 (NT), batched over (b,e)
  reset();
  p.A = qkv; p.lda = HD_P; p.as1 = 3LL * n * HD_P;
  p.Bm = qkv + (long long)n * HD_P; p.ldb = HD_P; p.bs1 = 3LL * n * HD_P;
  p.C = sco; p.ldc = n4; p.cs1 = (long long)n * n4;
  p.M = n; p.N = n; p.K = HD;
  p.scale = 0.14142135623730950488f;  // 1/sqrt(50)
  sgemm2_k<128, 128, 16, 8, 8, 1, 2>
      <<<dim3(cdiv(n, 128), cdiv(n, 128), B * E), 256>>>(p);

  softmax_rows_k<<<dim3(n, B * E), 256>>>(sco, n, n4);

  // 4. y[:, e*HD:(e+1)*HD] = (P @ V) * routing[b, s, e]
  reset();
  p.A = sco; p.lda = n4; p.as1 = (long long)n * n4;
  p.Bm = qkv + 2LL * n * HD_P; p.ldb = HD_P; p.bs1 = 3LL * n * HD_P;
  p.C = y; p.ldc = D; p.cDiv = E; p.cs1 = (long long)n * D; p.cs2 = HD;
  p.M = n; p.N = HD; p.K = n;
  p.rout = rout; p.routN = n;
  sgemm2_k<128, 64, 16, 8, 4, 0, 3><<<dim3(1, cdiv(n, 128), B * E), 256>>>(p);

  // 5. a = y @ out_w + out_b
  reset();
  p.A = y; p.lda = D;
  p.Bm = w.ow + (long long)layer * D * D; p.ldb = D;
  p.bias = w.ob + (long long)layer * D;
  p.C = a; p.ldc = D;
  p.M = M; p.N = D; p.K = D;
  sgemm2_k<64, 128, 16, 4, 8, 0, 0>
      <<<dim3(cdiv(D, 128), cdiv(M, 64), 1), 256>>>(p);

  // 6. x1 = LN1(t + a)
  add_ln_k<<<M, 256>>>(t, a, w.l1g + (long long)layer * D,
                       w.l1b + (long long)layer * D, x1);

  // 7. h = gelu(x1 @ ff_w1 + ff_b1)
  reset();
  p.A = x1; p.lda = D;
  p.Bm = w.w1 + (long long)layer * D * F; p.ldb = F;
  p.bias = w.b1 + (long long)layer * F;
  p.C = h; p.ldc = F;
  p.M = M; p.N = F; p.K = D;
  sgemm2_k<64, 128, 16, 4, 8, 0, 1>
      <<<dim3(cdiv(F, 128), cdiv(M, 64), 1), 256>>>(p);

  // 8. f = h @ ff_w2 + ff_b2 (into y, reuse)
  reset();
  p.A = h; p.lda = F;
  p.Bm = w.w2 + (long long)layer * F * D; p.ldb = D;
  p.bias = w.b2 + (long long)layer * D;
  p.C = y; p.ldc = D;
  p.M = M; p.N = D; p.K = F;
  sgemm2_k<64, 128, 16, 4, 8, 0, 0>
      <<<dim3(cdiv(D, 128), cdiv(M, 64), 1), 256>>>(p);

  // 9. out = LN2(x1 + f)
  add_ln_k<<<M, 256>>>(x1, y, w.l2g + (long long)layer * D,
                       w.l2b + (long long)layer * D, out);
}

extern "C" void kernel_launch(void* const* d_in, const int* in_sizes, int n_in,
                              void* d_out, int out_size) {
  (void)in_sizes; (void)n_in; (void)out_size;
  float* sc = nullptr;
  cudaGetSymbolAddress((void**)&sc, g_scratch);

  const float* x_in = (const float*)d_in[0];
  Wts w;
  w.ew = (const float*)d_in[1];  w.eb = (const float*)d_in[2];
  w.rw = (const float*)d_in[3];  w.rb = (const float*)d_in[4];
  w.ow = (const float*)d_in[5];  w.ob = (const float*)d_in[6];
  w.l1g = (const float*)d_in[7]; w.l1b = (const float*)d_in[8];
  w.w1 = (const float*)d_in[9];  w.b1 = (const float*)d_in[10];
  w.w2 = (const float*)d_in[11]; w.b2 = (const float*)d_in[12];
  w.l2g = (const float*)d_in[13]; w.l2b = (const float*)d_in[14];

  copy_k<<<cdiv((int)NX, 256), 256>>>(sc + OFF_X, x_in, NX);

  // Block 0 on full sequence (in-place into X is safe: t unused by final LN)
  run_block(sc, sc + OFF_X, sc + OFF_X, 0, S, w);

  for (int c = 0; c < CYCLES; c++) {
    zero_k<<<cdiv((int)NX, 256), 256>>>(sc + OFF_XNEW, NX);
    for (int j = 0; j < 4; j++) {
      int nseg = SEG_N[j];
      int tot = B * nseg * D;
      gather_k<<<cdiv(tot, 256), 256>>>(sc + OFF_T, sc + OFF_X, nseg, SEG_ST[j],
                                        SEG_P1[j]);
      run_block(sc, sc + OFF_T, sc + OFF_A, 1 + 4 * c + j, nseg, w);
      scatter_add_k<<<cdiv(tot, 256), 256>>>(sc + OFF_XNEW, sc + OFF_A, nseg,
                                             SEG_ST[j], SEG_P1[j]);
    }
    div_counts_k<<<cdiv((int)NX, 256), 256>>>(sc + OFF_X, sc + OFF_XNEW);
  }

  run_block(sc, sc + OFF_X, (float*)d_out, 13, S, w);
}